// round 17
// baseline (speedup 1.0000x reference)
#include <cuda_runtime.h>
#include <cuda_fp16.h>
#include <cstdint>

// ---------------- problem constants ----------------
#define B     4096
#define NS    26
#define DNS   13
#define D     16
#define V     100000
#define F     128
#define NN    39          // N = NS + DNS
#define DIN   429         // NS*D + DNS
#define H0S   448         // h0 padded K (429 -> 448), pad cols stay zero
#define D1    1024
#define D2    512
#define D3    256
#define MTOT  (B*D)       // 65536 rows for CIN GEMMs
#define EPSBN 1e-5f

// CIN chunking: k = n*C + c, chunks of 32 k (2 mma k16-steps per chunk)
#define C0P   64                  // layer0 c padded 39->64
#define NCH0  (NN*(C0P/32))       // 78  (even)
#define NCH12 (NN*(128/32))       // 156 (even)

#define XJSCALE  256.0f           // fp16 underflow guard on xj
#define XJISCALE (1.0f/256.0f)

// MLP fragment-W sizes: (NO/128 col-blocks) * (K/32 chunks) * 2048 u32
#define WM0_SZ  (8*14*2048)
#define WM1_SZ  (4*32*2048)
#define WM2_SZ  (2*16*2048)

// ---------------- device scratch (static, allowed; zero-initialized) ----------------
__device__ float    g_x0[(size_t)MTOT * NN];       // x0: [(b,d)][n]
__device__ uint32_t g_Wr0[(size_t)NCH0  * 2048];   // CIN W fp16x2, mma-fragment order
__device__ uint32_t g_Wr1[(size_t)NCH12 * 2048];
__device__ uint32_t g_Wr2[(size_t)NCH12 * 2048];
__device__ uint32_t g_Wm0[WM0_SZ];                 // MLP W fp16x2, mma-fragment order
__device__ uint32_t g_Wm1[WM1_SZ];
__device__ uint32_t g_Wm2[WM2_SZ];
__device__ float    g_h0[(size_t)B * H0S];         // padded; pad cols stay 0
__device__ float    g_h1[(size_t)B * D1];
__device__ float    g_h2[(size_t)B * D2];
__device__ float    g_h3[(size_t)B * D3];
__device__ float    g_p [(size_t)B * 3 * F];
__device__ float    g_lin[B];

__device__ __forceinline__ uint32_t packh2(float a, float b) {
    __half2 h = __floats2half2_rn(a, b);
    return *(uint32_t*)&h;
}
__device__ __forceinline__ uint32_t hmul2u(uint32_t a, uint32_t b) {
    uint32_t r; asm("mul.rn.f16x2 %0, %1, %2;" : "=r"(r) : "r"(a), "r"(b)); return r;
}
__device__ __forceinline__ uint32_t smem_u32(const void* p) {
    return (uint32_t)__cvta_generic_to_shared(p);
}
__device__ __forceinline__ void cp_async16(uint32_t dst, const void* src) {
    asm volatile("cp.async.cg.shared.global [%0], [%1], 16;" :: "r"(dst), "l"(src));
}
#define CP_COMMIT() asm volatile("cp.async.commit_group;")
#define CP_WAIT4()  asm volatile("cp.async.wait_group 4;")
#define CP_WAIT0()  asm volatile("cp.async.wait_group 0;")

#define MMA16816(acc, a0, a1, a2, a3, b0, b1) \
    asm volatile( \
        "mma.sync.aligned.m16n8k16.row.col.f32.f16.f16.f32 " \
        "{%0,%1,%2,%3}, {%4,%5,%6,%7}, {%8,%9}, {%0,%1,%2,%3};" \
        : "+f"((acc)[0]), "+f"((acc)[1]), "+f"((acc)[2]), "+f"((acc)[3]) \
        : "r"(a0), "r"(a1), "r"(a2), "r"(a3), "r"(b0), "r"(b1))

// ---------------- prep: gather embeddings, build x0 / h0 / linear part ----------------
__global__ void prep_kernel(const float* __restrict__ dense_x,
                            const int*   __restrict__ disc,
                            const float* __restrict__ lin_emb,
                            const float* __restrict__ emb_W,
                            const float* __restrict__ dense_W,
                            const float* __restrict__ dense_b,
                            const float* __restrict__ dense_proj)
{
    int b = blockIdx.x;
    int lane = threadIdx.x;          // 32 threads
    float linacc = 0.f;

    if (lane < NS) {
        int idx = disc[b * NS + lane];
        const float4* src = reinterpret_cast<const float4*>(
            emb_W + ((size_t)lane * V + (size_t)idx) * D);
        float e[16];
        #pragma unroll
        for (int j = 0; j < 4; j++) {
            float4 v = src[j];
            e[4*j+0] = v.x; e[4*j+1] = v.y; e[4*j+2] = v.z; e[4*j+3] = v.w;
        }
        #pragma unroll
        for (int j = 0; j < 16; j++) {
            g_h0[(size_t)b * H0S + lane * 16 + j] = e[j];
            g_x0[((size_t)(b * D + j)) * NN + lane] = e[j];
        }
        linacc += lin_emb[(size_t)lane * V + idx];
    }
    if (lane < DNS) {
        float v = dense_x[b * DNS + lane];
        g_h0[(size_t)b * H0S + NS * D + lane] = v;
        #pragma unroll
        for (int d = 0; d < D; d++)
            g_x0[((size_t)(b * D + d)) * NN + NS + lane] = v * dense_proj[lane * D + d];
        linacc += v * dense_W[lane];
    }
    #pragma unroll
    for (int o = 16; o; o >>= 1) linacc += __shfl_down_sync(0xffffffffu, linacc, o);
    if (lane == 0) g_lin[b] = linacc + dense_b[0];
}

// ---------------- CIN W reorder into fp16 mma-fragment order -------------------------
// Chunk ch: n = ch/(C/32), cbase = (ch mod (C/32))*32. u32 slot
// u = ((s2*16 + t)*32 + lane)*2 + p holds half2 { Wt[k][f], Wt[k+1][f] } with
// k = s2*16 + p*8 + (lane&3)*2, f = t*8 + (lane>>2).
__global__ void prep_w_kernel(const float* __restrict__ W0,
                              const float* __restrict__ W1,
                              const float* __restrict__ W2)
{
    int idx = blockIdx.x * 256 + threadIdx.x;
    const int S0 = NCH0 * 2048, S12 = NCH12 * 2048;
    uint32_t* dst; const float* W; int C, rem, isL0 = 0;
    if (idx < S0)              { dst = g_Wr0; rem = idx;            C = C0P; W = W0; isL0 = 1; }
    else if (idx < S0 + S12)   { dst = g_Wr1; rem = idx - S0;       C = 128; W = W1; }
    else if (idx < S0 + 2*S12) { dst = g_Wr2; rem = idx - S0 - S12; C = 128; W = W2; }
    else return;

    int ch = rem >> 11, u = rem & 2047;
    int s2   = u >> 10;
    int t    = (u >> 6) & 15;
    int lane = (u >> 1) & 31;
    int p    = u & 1;
    int kl = s2 * 16 + p * 8 + (lane & 3) * 2;
    int f  = t * 8 + (lane >> 2);
    int n  = ch / (C / 32);
    int c0 = (ch % (C / 32)) * 32 + kl;
    float v0, v1;
    if (isL0) {
        v0 = (c0     < NN) ? W[(f * NN + c0    ) * NN + n] : 0.f;
        v1 = (c0 + 1 < NN) ? W[(f * NN + c0 + 1) * NN + n] : 0.f;
    } else {
        v0 = W[(f * 128 + c0    ) * NN + n];
        v1 = W[(f * 128 + c0 + 1) * NN + n];
    }
    dst[rem] = packh2(v0, v1);
}

// ---------------- MLP W reorder into fp16 mma-fragment order -------------------------
__global__ void prep_wm_kernel(const float* __restrict__ W1,
                               const float* __restrict__ W2,
                               const float* __restrict__ W3)
{
    int idx = blockIdx.x * 256 + threadIdx.x;
    uint32_t* dst; const float* W; int rem, NO, Kreal;
    if (idx < WM0_SZ)                    { dst = g_Wm0; rem = idx;                    W = W1; NO = D1; Kreal = DIN; }
    else if (idx < WM0_SZ + WM1_SZ)      { dst = g_Wm1; rem = idx - WM0_SZ;           W = W2; NO = D2; Kreal = D1; }
    else if (idx < WM0_SZ + WM1_SZ + WM2_SZ) { dst = g_Wm2; rem = idx - WM0_SZ - WM1_SZ; W = W3; NO = D3; Kreal = D2; }
    else return;

    int NCH = (dst == g_Wm0) ? 14 : (dst == g_Wm1) ? 32 : 16;
    int cbch = rem >> 11, u = rem & 2047;
    int ch = cbch % NCH, cb = cbch / NCH;
    int s2   = u >> 10;
    int t    = (u >> 6) & 15;
    int lane = (u >> 1) & 31;
    int p    = u & 1;
    int k = ch * 32 + s2 * 16 + p * 8 + (lane & 3) * 2;
    int f = cb * 128 + t * 8 + (lane >> 2);
    float v0 = (k     < Kreal) ? W[(size_t)k       * NO + f] : 0.f;
    float v1 = (k + 1 < Kreal) ? W[(size_t)(k + 1) * NO + f] : 0.f;
    dst[rem] = packh2(v0, v1);
}

// ---------------- FUSED CIN: all 3 layers in one kernel -------------------------------
// Per CTA: 128 m-rows. Layer L output tile is written straight into xj_s (fragment-
// interleaved fp16, scales cancel) for layer L+1. 6-stage cp.async ring, chunk PAIRS
// per barrier (one __syncthreads per 64 MMAs/warp).
__global__ void __launch_bounds__(256, 2)
cin_fused_kernel()
{
    constexpr int XJH = 72;                      // half2 units/row; 72 % 32 == 8

    extern __shared__ char smem[];
    uint32_t* wbuf = (uint32_t*)smem;            // 6 x 2048 u32 cp.async ring
    uint32_t* xj_s = (uint32_t*)(smem + 49152);  // [128][XJH] fp16x2
    uint32_t* x0h  = xj_s + 128 * XJH;           // [NN][128] dup-half2

    int tid = threadIdx.x, m0 = blockIdx.x * 128;
    int wm = tid >> 5, lane = tid & 31, gid = lane >> 2, qid = lane & 3;
    int fq = wm >> 1, rh = wm & 1;
    int rbase = rh * 64;
    uint32_t wsm = smem_u32(wbuf);

    // prime ring with L0 chunks 0..3 (4 commit groups; overlaps staging)
    #pragma unroll
    for (int c = 0; c < 4; c++) {
        uint32_t dst = wsm + c * 8192;
        cp_async16(dst + tid * 16,        g_Wr0 + (size_t)c * 2048 + tid * 4);
        cp_async16(dst + 4096 + tid * 16, g_Wr0 + (size_t)c * 2048 + 1024 + tid * 4);
        CP_COMMIT();
    }

    // stage xj for L0 (scaled x0, fragment-pair interleave; blk 0..3 only)
    for (int i = tid; i < 128 * 32; i += 256) {
        int r = i >> 5, pr = i & 31, c = pr * 2;
        float v0 = (c     < NN) ? g_x0[(size_t)(m0 + r) * NN + c    ] * XJSCALE : 0.f;
        float v1 = (c + 1 < NN) ? g_x0[(size_t)(m0 + r) * NN + c + 1] * XJSCALE : 0.f;
        int slot = (c >> 4) * 8 + (((c & 15) >> 1) & 3) * 2 + (((c & 15) >> 3) & 1);
        xj_s[r * XJH + slot] = packh2(v0, v1);
    }
    // stage x0 column-major dup-half2 (once for all layers)
    for (int i = tid; i < NN * 128; i += 256) {
        int n = i >> 7, m = i & 127;
        __half2 h = __float2half2_rn(g_x0[(size_t)(m0 + m) * NN + n]);
        x0h[i] = *(uint32_t*)&h;
    }

    float acc[4][4][4];

    for (int L = 0; L < 3; L++) {
        const uint32_t* __restrict__ Wr = (L == 0) ? g_Wr0 : (L == 1) ? g_Wr1 : g_Wr2;
        const int NCHK = (L == 0) ? NCH0 : NCH12;
        const int csh  = (L == 0) ? 1 : 2;
        const int cmask = (1 << csh) - 1;

        #pragma unroll
        for (int bk = 0; bk < 4; bk++)
            #pragma unroll
            for (int t = 0; t < 4; t++)
                #pragma unroll
                for (int q = 0; q < 4; q++) acc[bk][t][q] = 0.f;

        for (int ch = 0; ch < NCHK; ch += 2) {
            // feed chunks ch+4, ch+5 (one commit group each; empty groups kept)
            #pragma unroll
            for (int h = 0; h < 2; h++) {
                int c = ch + 4 + h;
                if (c < NCHK) {
                    const uint32_t* src = Wr + (size_t)c * 2048;
                    uint32_t dst = wsm + (c % 6) * 8192;
                    cp_async16(dst + tid * 16,        src + tid * 4);
                    cp_async16(dst + 4096 + tid * 16, src + 1024 + tid * 4);
                }
                CP_COMMIT();
            }
            CP_WAIT4();                          // chunks ch, ch+1 landed
            __syncthreads();

            #pragma unroll
            for (int h = 0; h < 2; h++) {
                int cc = ch + h;
                int n    = cc >> csh;
                int blk0 = (cc & cmask) * 2;
                uint32_t x0r[8];
                #pragma unroll
                for (int j = 0; j < 8; j++) x0r[j] = x0h[n * 128 + rbase + gid + 8 * j];
                const uint2* wfr = (const uint2*)(wbuf + (cc % 6) * 2048);

                #pragma unroll
                for (int s2 = 0; s2 < 2; s2++) {
                    int blk = blk0 + s2;
                    uint32_t alo[8], ahi[8];
                    #pragma unroll
                    for (int j = 0; j < 8; j++) {
                        uint2 xp = *(const uint2*)(xj_s + (rbase + gid + 8 * j) * XJH + blk * 8 + qid * 2);
                        alo[j] = hmul2u(xp.x, x0r[j]);
                        ahi[j] = hmul2u(xp.y, x0r[j]);
                    }
                    #pragma unroll
                    for (int t = 0; t < 4; t++) {
                        uint2 bf = wfr[(s2 * 16 + fq * 4 + t) * 32 + lane];
                        #pragma unroll
                        for (int bk = 0; bk < 4; bk++)
                            MMA16816(acc[bk][t], alo[2*bk], alo[2*bk+1], ahi[2*bk], ahi[2*bk+1],
                                     bf.x, bf.y);
                    }
                }
            }
        }

        CP_WAIT0();
        __syncthreads();                         // all compute done; xj_s reusable

        // re-prime ring for next layer (overlaps epilogue)
        if (L < 2) {
            const uint32_t* Wn = (L == 0) ? g_Wr1 : g_Wr2;
            #pragma unroll
            for (int c = 0; c < 4; c++) {
                uint32_t dst = wsm + c * 8192;
                cp_async16(dst + tid * 16,        Wn + (size_t)c * 2048 + tid * 4);
                cp_async16(dst + 4096 + tid * 16, Wn + (size_t)c * 2048 + 1024 + tid * 4);
                CP_COMMIT();
            }
        }

        // epilogue: p_l + (L<2) next-layer xj into xj_s.
        // acc = 256 * y; store raw acc as next xj (scales cancel).
        #pragma unroll
        for (int bk = 0; bk < 4; bk++) {
            int r0 = rbase + bk * 16 + gid;
            #pragma unroll
            for (int t = 0; t < 4; t++) {
                int col = fq * 32 + t * 8 + 2 * qid;
                if (L < 2) {
                    int slot = (fq * 2 + (t >> 1)) * 8 + qid * 2 + (t & 1);
                    xj_s[r0 * XJH + slot]       = packh2(acc[bk][t][0], acc[bk][t][1]);
                    xj_s[(r0 + 8) * XJH + slot] = packh2(acc[bk][t][2], acc[bk][t][3]);
                }
                float v0 = acc[bk][t][0] + acc[bk][t][2];
                float v1 = acc[bk][t][1] + acc[bk][t][3];
                #pragma unroll
                for (int o = 4; o <= 16; o <<= 1) {
                    v0 += __shfl_xor_sync(0xffffffffu, v0, o);
                    v1 += __shfl_xor_sync(0xffffffffu, v1, o);
                }
                if (gid == 0) {
                    int bidx = (m0 >> 4) + rh * 4 + bk;
                    float* pp = g_p + (size_t)bidx * (3 * F) + L * F + col;
                    pp[0] = v0 * XJISCALE;
                    pp[1] = v1 * XJISCALE;
                }
            }
        }
        if (L < 2) __syncthreads();              // xj_s ready for next layer
    }
}

// ---------------- MLP layer via mma.sync m16n8k16 fp16 + bias + BN + ReLU ------------
template<int STAGE>
__global__ void __launch_bounds__(256, 2)
mlp_mma_kernel(const float* __restrict__ bias, const float* __restrict__ bng,
               const float* __restrict__ bnb)
{
    constexpr int K   = (STAGE == 0) ? H0S : (STAGE == 1) ? D1 : D2;   // padded K
    constexpr int NO  = (STAGE == 0) ? D1  : (STAGE == 1) ? D2 : D3;
    constexpr int NCH = K / 32;
    constexpr int AST = 24;                       // u32 row stride (≡24 mod 32)

    __shared__ uint32_t wbuf[2][2048];
    __shared__ uint32_t abuf[2][128 * AST];

    const float* __restrict__ A  = (STAGE == 0) ? g_h0 : (STAGE == 1) ? g_h1 : g_h2;
    float* __restrict__ O        = (STAGE == 0) ? g_h1 : (STAGE == 1) ? g_h2 : g_h3;
    const uint32_t* __restrict__ Wm = (STAGE == 0) ? g_Wm0 : (STAGE == 1) ? g_Wm1 : g_Wm2;

    int tid = threadIdx.x;
    int m0 = blockIdx.y * 128, cb = blockIdx.x, n0 = cb * 128;
    int wm = tid >> 5, lane = tid & 31;
    int gid = lane >> 2, qid = lane & 3;
    int fq = wm >> 1, rh = wm & 1;
    int rbase = rh * 64;

    const uint32_t* Wbase = Wm + (size_t)cb * NCH * 2048;

    // A staging indices: 2 threads/row, 16 k each
    int ar = tid >> 1, ah = (tid & 1) * 16;

    // prefetch chunk 0
    uint4 wpa = ((const uint4*)Wbase)[tid];
    uint4 wpb = ((const uint4*)Wbase)[tid + 256];
    float4 apf[4];
    #pragma unroll
    for (int i = 0; i < 4; i++)
        apf[i] = *(const float4*)(A + (size_t)(m0 + ar) * K + ah + i * 4);

    float acc[4][4][4];
    #pragma unroll
    for (int bk = 0; bk < 4; bk++)
        #pragma unroll
        for (int t = 0; t < 4; t++)
            #pragma unroll
            for (int q = 0; q < 4; q++) acc[bk][t][q] = 0.f;

    for (int ch = 0; ch < NCH; ch++) {
        int st = ch & 1;
        ((uint4*)wbuf[st])[tid]       = wpa;
        ((uint4*)wbuf[st])[tid + 256] = wpb;
        #pragma unroll
        for (int i = 0; i < 4; i++) {
            float4 v = apf[i];
            int c = ah + i * 4;
            int blk = c >> 4, rel = c & 15;
            int s0 = blk * 8 + ((rel >> 1) & 3) * 2 + ((rel >> 3) & 1);
            int rel2 = (c + 2) & 15;
            int s1 = blk * 8 + ((rel2 >> 1) & 3) * 2 + ((rel2 >> 3) & 1);
            abuf[st][ar * AST + s0] = packh2(v.x, v.y);
            abuf[st][ar * AST + s1] = packh2(v.z, v.w);
        }
        __syncthreads();
        if (ch + 1 < NCH) {
            const uint4* wg = (const uint4*)(Wbase + (size_t)(ch + 1) * 2048);
            wpa = wg[tid]; wpb = wg[tid + 256];
            #pragma unroll
            for (int i = 0; i < 4; i++)
                apf[i] = *(const float4*)(A + (size_t)(m0 + ar) * K + (ch + 1) * 32 + ah + i * 4);
        }

        const uint2* wfr = (const uint2*)wbuf[st];
        #pragma unroll
        for (int s2 = 0; s2 < 2; s2++) {
            uint32_t alo[8], ahi[8];
            #pragma unroll
            for (int j = 0; j < 8; j++) {
                uint2 xp = *(const uint2*)(abuf[st] + (rbase + gid + 8 * j) * AST + s2 * 8 + qid * 2);
                alo[j] = xp.x; ahi[j] = xp.y;
            }
            #pragma unroll
            for (int t = 0; t < 4; t++) {
                uint2 bf = wfr[(s2 * 16 + fq * 4 + t) * 32 + lane];
                #pragma unroll
                for (int bk = 0; bk < 4; bk++)
                    MMA16816(acc[bk][t], alo[2*bk], alo[2*bk+1], ahi[2*bk], ahi[2*bk+1],
                             bf.x, bf.y);
            }
        }
    }

    // epilogue: bias + BN(eval) + ReLU
    float rs = rsqrtf(1.f + EPSBN);
    #pragma unroll
    for (int t = 0; t < 4; t++) {
        int col = n0 + fq * 32 + t * 8 + 2 * qid;
        float2 bi = *(const float2*)(bias + col);
        float2 gg = *(const float2*)(bng + col);
        float2 sh = *(const float2*)(bnb + col);
        float s0 = gg.x * rs, s1 = gg.y * rs;
        #pragma unroll
        for (int bk = 0; bk < 4; bk++) {
            int r0 = m0 + rbase + bk * 16 + gid;
            float2 lo, hi;
            lo.x = fmaxf(0.f, (acc[bk][t][0] + bi.x) * s0 + sh.x);
            lo.y = fmaxf(0.f, (acc[bk][t][1] + bi.y) * s1 + sh.y);
            hi.x = fmaxf(0.f, (acc[bk][t][2] + bi.x) * s0 + sh.x);
            hi.y = fmaxf(0.f, (acc[bk][t][3] + bi.y) * s1 + sh.y);
            *(float2*)(O + (size_t)r0 * NO + col)       = lo;
            *(float2*)(O + (size_t)(r0 + 8) * NO + col) = hi;
        }
    }
}

// ---------------- final combine ----------------
__global__ void final_kernel(const float* __restrict__ Wout, const float* __restrict__ bout,
                             const float* __restrict__ cW,   const float* __restrict__ cb,
                             float* __restrict__ out)
{
    int b = blockIdx.x, tid = threadIdx.x;      // 128 threads
    float acc = 0.f;
    for (int i = tid; i < D3; i += 128)     acc += g_h3[(size_t)b * D3 + i] * Wout[i];
    for (int i = tid; i < 3 * F; i += 128)  acc += g_p[(size_t)b * (3 * F) + i] * cW[i];
    __shared__ float sm[4];
    #pragma unroll
    for (int o = 16; o; o >>= 1) acc += __shfl_down_sync(0xffffffffu, acc, o);
    if ((tid & 31) == 0) sm[tid >> 5] = acc;
    __syncthreads();
    if (tid == 0)
        out[b] = sm[0] + sm[1] + sm[2] + sm[3] + g_lin[b] + bout[0] + cb[0];
}

// ---------------- launch ----------------
extern "C" void kernel_launch(void* const* d_in, const int* in_sizes, int n_in,
                              void* d_out, int out_size)
{
    const float* dense_x    = (const float*)d_in[0];
    const int*   discrete_x = (const int*)  d_in[1];
    const float* lin_emb    = (const float*)d_in[2];
    const float* emb_W      = (const float*)d_in[3];
    const float* dense_W    = (const float*)d_in[4];
    const float* dense_b    = (const float*)d_in[5];
    const float* W1         = (const float*)d_in[6];
    const float* b1         = (const float*)d_in[7];
    const float* bn1_g      = (const float*)d_in[8];
    const float* bn1_b      = (const float*)d_in[9];
    const float* W2         = (const float*)d_in[10];
    const float* b2         = (const float*)d_in[11];
    const float* bn2_g      = (const float*)d_in[12];
    const float* bn2_b      = (const float*)d_in[13];
    const float* W3         = (const float*)d_in[14];
    const float* b3         = (const float*)d_in[15];
    const float* bn3_g      = (const float*)d_in[16];
    const float* bn3_b      = (const float*)d_in[17];
    const float* Wout       = (const float*)d_in[18];
    const float* bout       = (const float*)d_in[19];
    const float* dense_proj = (const float*)d_in[20];
    const float* cin_W0     = (const float*)d_in[21];
    const float* cin_W1     = (const float*)d_in[22];
    const float* cin_W2     = (const float*)d_in[23];
    const float* cin_out_W  = (const float*)d_in[24];
    const float* cin_out_b  = (const float*)d_in[25];
    float* out = (float*)d_out;

    // fused CIN dynamic smem: ring 48KB + xj[128][72] u32 + x0h[NN][128] u32
    const int smemF = 49152 + 128 * 72 * 4 + NN * 128 * 4;   // 105984
    cudaFuncSetAttribute(cin_fused_kernel, cudaFuncAttributeMaxDynamicSharedMemorySize, smemF);

    prep_kernel<<<B, 32>>>(dense_x, discrete_x, lin_emb, emb_W,
                           dense_W, dense_b, dense_proj);

    int wtot = (NCH0 + 2 * NCH12) * 2048;
    prep_w_kernel<<<(wtot + 255) / 256, 256>>>(cin_W0, cin_W1, cin_W2);
    int wmtot = WM0_SZ + WM1_SZ + WM2_SZ;
    prep_wm_kernel<<<(wmtot + 255) / 256, 256>>>(W1, W2, W3);

    // fused CIN (all 3 layers, y in smem, p emitted directly, chunk-pair barriers)
    cin_fused_kernel<<<MTOT / 128, 256, smemF>>>();

    // DNN on tensor cores
    mlp_mma_kernel<0><<<dim3(D1 / 128, B / 128), 256>>>(b1, bn1_g, bn1_b);
    mlp_mma_kernel<1><<<dim3(D2 / 128, B / 128), 256>>>(b2, bn2_g, bn2_b);
    mlp_mma_kernel<2><<<dim3(D3 / 128, B / 128), 256>>>(b3, bn3_g, bn3_b);

    final_kernel<<<B, 128>>>(Wout, bout, cin_out_W, cin_out_b, out);
}